// round 2
// baseline (speedup 1.0000x reference)
#include <cuda_runtime.h>
#include <math.h>

#define DINLINE __device__ __forceinline__

// ---------------------------------------------------------------------------
// Fixed problem dimensions (B=4, grid 513, coef 512, epoch=101 -> K=2)
// ---------------------------------------------------------------------------
namespace fns {
constexpr int NB = 4;
constexpr int NG = 513;              // grid nodes per side
constexpr int NI = 511;              // interior nodes per side
constexpr int NC = 512;              // coefficient cells per side
constexpr long long NN  = (long long)NG * NG;    // 263169
constexpr long long NCC = (long long)NC * NC;
constexpr long long NII = (long long)NI * NI;
constexpr long long NIG = (long long)NI * NG;    // 511*513
constexpr int NBLK_A = 128;          // alpha partial blocks per batch
constexpr int NBLK_N = 256;          // norm partial blocks
constexpr int KSTEPS = 2;            // (101-1)//100 + 1
}
using namespace fns;

// ---------------------------------------------------------------------------
// Static device scratch (runtime allocation is forbidden)
// ---------------------------------------------------------------------------
__device__ float  g_x   [NB * NN];
__device__ float  g_x2  [NB * NN];
__device__ float  g_r   [NB * NN];
__device__ float  g_e   [NB * NN];
__device__ float  g_dinv[NB * NII];
__device__ float  g_S   [NG * (long long)NI];  // Ssp[p][j] = sin(pi (p-256)(j+1)/512), ld=NI
__device__ float  g_St  [NIG];                 // Sjp[j][p] (transpose), ld=NG
__device__ float2 g_G   [NIG];                 // G[s][u] = exp(-2pi i s(u-255)/1025), ld=NG
__device__ float2 g_Gt  [NIG];                 // Gt[u][s], ld=NI
__device__ float  g_U   [NB * NIG];            // r_int * Sjp, 511 x 513, ld=NG
__device__ float2 g_cA  [NB * 4 * NN];
__device__ float2 g_cB  [NB * 4 * NN];
__device__ float2 g_cC  [NB * NN];
__device__ float2 g_W   [NB * NIG];            // T = out * Gt, 513 x 511, ld=NI
__device__ double g_pd1 [2048];
__device__ double g_pd2 [2048];
__device__ float  g_alpha[NB];

// ---------------------------------------------------------------------------
// Darcy FEM 9-point stencil at interior node (i,j), i,j in [1, NG-2].
// Derived from the reference 4-channel 2x2 VALID conv.
// ---------------------------------------------------------------------------
DINLINE float darcy_at(const float* __restrict__ x,
                       const float* __restrict__ a, int i, int j)
{
    const float c23 = 2.f / 3.f, c16 = -1.f / 6.f, c13 = -1.f / 3.f;
    float s = 0.f;
#pragma unroll
    for (int u = 0; u < 2; u++) {
#pragma unroll
        for (int v = 0; v < 2; v++) {
            int I = i - 1 + u, J = j - 1 + v;
            float av = a[(long long)I * NC + J];
            // K3 on x[I,J], K2 on x[I,J+1], K0 on x[I+1,J], K1 on x[I+1,J+1]
            float k0, k1, k2, k3;
            if (u == 0 && v == 0) { k0 = c16; k1 = c23; k2 = c16; k3 = c13; }
            else if (u == 0 && v == 1) { k0 = c23; k1 = c16; k2 = c13; k3 = c16; }
            else if (u == 1 && v == 0) { k0 = c13; k1 = c16; k2 = c23; k3 = c16; }
            else                        { k0 = c16; k1 = c13; k2 = c16; k3 = c23; }
            s += av * (k3 * x[(long long)I * NG + J]
                     + k2 * x[(long long)I * NG + J + 1]
                     + k0 * x[(long long)(I + 1) * NG + J]
                     + k1 * x[(long long)(I + 1) * NG + J + 1]);
        }
    }
    return s;
}

// ---------------------------------------------------------------------------
// Setup kernels
// ---------------------------------------------------------------------------
__global__ void k_precS(float* __restrict__ S, float* __restrict__ St)
{
    int idx = blockIdx.x * blockDim.x + threadIdx.x;
    if (idx >= NG * NI) return;
    int p = idx / NI, j = idx - p * NI;
    int m = (j + 1) * (p - 256);             // exact in int
    int mm = ((m % 1024) + 1024) % 1024;     // sin(pi*m/512): period 1024 in m
    float v = sinpif((float)mm / 512.f);
    S[idx] = v;
    St[(long long)j * NG + p] = v;
}

__global__ void k_precG(float2* __restrict__ G, float2* __restrict__ Gt)
{
    int idx = blockIdx.x * blockDim.x + threadIdx.x;
    if (idx >= NI * NG) return;
    int s = idx / NG, u = idx - s * NG;
    int t = (u - 255) * s;                   // exp(-2pi i t/1025): period 1025
    int tm = ((t % 1025) + 1025) % 1025;
    float xr = 2.f * (float)tm / 1025.f;
    float2 g = make_float2(cospif(xr), -sinpif(xr));
    G[idx] = g;
    Gt[(long long)u * NI + s] = g;
}

__global__ void k_dinv(const float* __restrict__ a, float* __restrict__ dinv)
{
    int b = blockIdx.z;
    int q = blockIdx.x * 16 + threadIdx.x;
    int p = blockIdx.y * 16 + threadIdx.y;
    if (p >= NI || q >= NI) return;
    const float* ap = a + (long long)b * NCC;
    float s = ap[(long long)p * NC + q] + ap[(long long)p * NC + q + 1]
            + ap[(long long)(p + 1) * NC + q] + ap[(long long)(p + 1) * NC + q + 1];
    dinv[(long long)b * NII + (long long)p * NI + q] = 1.f / ((2.f / 3.f) * s);
}

__global__ void k_zero3(float* __restrict__ x, float* __restrict__ x2,
                        float* __restrict__ e)
{
    long long idx = (long long)blockIdx.x * blockDim.x + threadIdx.x;
    long long tot = (long long)NB * NN;
    if (idx >= tot) return;
    x[idx] = 0.f; x2[idx] = 0.f; e[idx] = 0.f;
}

// ---------------------------------------------------------------------------
// Jacobi sweep (interior only; boundaries stay 0 forever) and residual
// ---------------------------------------------------------------------------
__global__ __launch_bounds__(256)
void k_jacobi(const float* __restrict__ xin, float* __restrict__ xout,
              const float* __restrict__ f, const float* __restrict__ a,
              const float* __restrict__ dinv)
{
    int b = blockIdx.z;
    int j = blockIdx.x * 16 + threadIdx.x + 1;
    int i = blockIdx.y * 16 + threadIdx.y + 1;
    if (i > NI || j > NI) return;
    const float* xp = xin + (long long)b * NN;
    const float* ap = a + (long long)b * NCC;
    long long o = (long long)b * NN + (long long)i * NG + j;
    float d = darcy_at(xp, ap, i, j);
    float r = f[o] - d;
    xout[o] = xp[(long long)i * NG + j]
            + 0.75f * dinv[(long long)b * NII + (long long)(i - 1) * NI + (j - 1)] * r;
}

__global__ __launch_bounds__(256)
void k_resid(const float* __restrict__ x, const float* __restrict__ f,
             const float* __restrict__ a, float* __restrict__ r)
{
    int b = blockIdx.z;
    int j = blockIdx.x * 16 + threadIdx.x;
    int i = blockIdx.y * 16 + threadIdx.y;
    if (i >= NG || j >= NG) return;
    long long o = (long long)b * NN + (long long)i * NG + j;
    float d = 0.f;
    if (i > 0 && j > 0 && i < NG - 1 && j < NG - 1)
        d = darcy_at(x + (long long)b * NN, a + (long long)b * NCC, i, j);
    r[o] = f[o] - d;
}

// ---------------------------------------------------------------------------
// Real SGEMM, C = alpha * A(MxK) * B(KxN), NN layout, batched via blockIdx.z.
// 64x64 tile, BK=16, 256 threads, 4x4 microtile. CPLX_OUT writes float2(v,0).
// ---------------------------------------------------------------------------
template<bool CPLX_OUT>
__global__ __launch_bounds__(256)
void k_sgemm(const float* __restrict__ A, int lda, long long sA,
             const float* __restrict__ B, int ldb, long long sB,
             void* __restrict__ Cv, int ldc, long long sC,
             int M, int N, int K, float alpha)
{
    __shared__ float As[16][68];
    __shared__ float Bs[16][68];
    int b = blockIdx.z;
    A += (long long)b * sA;
    B += (long long)b * sB;
    int tid = threadIdx.x;
    int m0 = blockIdx.y * 64, n0 = blockIdx.x * 64;
    int mt = (tid & 15) * 4;
    int nt = (tid >> 4) * 4;
    float acc[4][4] = {};

    for (int kt = 0; kt < K; kt += 16) {
#pragma unroll
        for (int e = 0; e < 4; e++) {
            int idx = tid + e * 256;
            int r = idx >> 4, c = idx & 15;
            int gm = m0 + r, gk = kt + c;
            As[c][r] = (gm < M && gk < K) ? A[(long long)gm * lda + gk] : 0.f;
            int r2 = idx >> 6, c2 = idx & 63;
            int gk2 = kt + r2, gn = n0 + c2;
            Bs[r2][c2] = (gk2 < K && gn < N) ? B[(long long)gk2 * ldb + gn] : 0.f;
        }
        __syncthreads();
#pragma unroll
        for (int k = 0; k < 16; k++) {
            float av[4], bv[4];
#pragma unroll
            for (int i = 0; i < 4; i++) av[i] = As[k][mt + i];
#pragma unroll
            for (int j = 0; j < 4; j++) bv[j] = Bs[k][nt + j];
#pragma unroll
            for (int i = 0; i < 4; i++)
#pragma unroll
                for (int j = 0; j < 4; j++)
                    acc[i][j] = fmaf(av[i], bv[j], acc[i][j]);
        }
        __syncthreads();
    }

#pragma unroll
    for (int i = 0; i < 4; i++) {
        int gm = m0 + mt + i;
        if (gm >= M) continue;
#pragma unroll
        for (int j = 0; j < 4; j++) {
            int gn = n0 + nt + j;
            if (gn >= N) continue;
            if (CPLX_OUT) {
                float2* C = (float2*)Cv;
                C[(long long)b * sC + (long long)gm * ldc + gn] =
                    make_float2(alpha * acc[i][j], 0.f);
            } else {
                float* C = (float*)Cv;
                C[(long long)b * sC + (long long)gm * ldc + gn] = alpha * acc[i][j];
            }
        }
    }
}

// ---------------------------------------------------------------------------
// Complex GEMM, C = A(MxK) * B(KxN), complex64. REAL_OUT keeps only Re.
// ---------------------------------------------------------------------------
DINLINE float2 cmad(float2 acc, float2 a, float2 b)
{
    acc.x = fmaf(a.x, b.x, fmaf(-a.y, b.y, acc.x));
    acc.y = fmaf(a.x, b.y, fmaf(a.y, b.x, acc.y));
    return acc;
}

template<bool REAL_OUT>
__global__ __launch_bounds__(256)
void k_cgemm(const float2* __restrict__ A, int lda, long long sA,
             const float2* __restrict__ B, int ldb, long long sB,
             void* __restrict__ Cv, int ldc, long long sC,
             int M, int N, int K)
{
    __shared__ float2 As[16][66];
    __shared__ float2 Bs[16][66];
    int b = blockIdx.z;
    A += (long long)b * sA;
    B += (long long)b * sB;
    int tid = threadIdx.x;
    int m0 = blockIdx.y * 64, n0 = blockIdx.x * 64;
    int mt = (tid & 15) * 4;
    int nt = (tid >> 4) * 4;
    float2 accc[4][4];
    float  accr[4][4];
#pragma unroll
    for (int i = 0; i < 4; i++)
#pragma unroll
        for (int j = 0; j < 4; j++) { accc[i][j] = make_float2(0.f, 0.f); accr[i][j] = 0.f; }

    for (int kt = 0; kt < K; kt += 16) {
#pragma unroll
        for (int e = 0; e < 4; e++) {
            int idx = tid + e * 256;
            int r = idx >> 4, c = idx & 15;
            int gm = m0 + r, gk = kt + c;
            As[c][r] = (gm < M && gk < K) ? A[(long long)gm * lda + gk] : make_float2(0.f, 0.f);
            int r2 = idx >> 6, c2 = idx & 63;
            int gk2 = kt + r2, gn = n0 + c2;
            Bs[r2][c2] = (gk2 < K && gn < N) ? B[(long long)gk2 * ldb + gn] : make_float2(0.f, 0.f);
        }
        __syncthreads();
#pragma unroll
        for (int k = 0; k < 16; k++) {
            float2 av[4], bv[4];
#pragma unroll
            for (int i = 0; i < 4; i++) av[i] = As[k][mt + i];
#pragma unroll
            for (int j = 0; j < 4; j++) bv[j] = Bs[k][nt + j];
#pragma unroll
            for (int i = 0; i < 4; i++)
#pragma unroll
                for (int j = 0; j < 4; j++) {
                    if (REAL_OUT) {
                        accr[i][j] = fmaf(av[i].x, bv[j].x,
                                     fmaf(-av[i].y, bv[j].y, accr[i][j]));
                    } else {
                        accc[i][j] = cmad(accc[i][j], av[i], bv[j]);
                    }
                }
        }
        __syncthreads();
    }

#pragma unroll
    for (int i = 0; i < 4; i++) {
        int gm = m0 + mt + i;
        if (gm >= M) continue;
#pragma unroll
        for (int j = 0; j < 4; j++) {
            int gn = n0 + nt + j;
            if (gn >= N) continue;
            if (REAL_OUT) {
                float* C = (float*)Cv;
                C[(long long)b * sC + (long long)gm * ldc + gn] = accr[i][j];
            } else {
                float2* C = (float2*)Cv;
                C[(long long)b * sC + (long long)gm * ldc + gn] = accc[i][j];
            }
        }
    }
}

// ---------------------------------------------------------------------------
// Complex multi-channel 3x3 conv (pad=1) on 513x513 images.
// conjt=1 applies conjT(w): channel-axes swap + spatial transpose + conjugate.
// Raw weight dims: (B, D1, D2, 3, 3) with (D1,D2) = (CO,CI) if !conjt else (CI,CO).
// ---------------------------------------------------------------------------
template<int CO, int CI>
__global__ __launch_bounds__(256)
void k_conv(const float2* __restrict__ X, float2* __restrict__ Y,
            const float* __restrict__ wr, const float* __restrict__ wi,
            int conjt)
{
    int b = blockIdx.z;
    __shared__ float2 ws[CO * CI * 9];
    int t = threadIdx.y * 16 + threadIdx.x;
    if (t < CO * CI * 9) {
        int o = t / (CI * 9), rem = t % (CI * 9), i = rem / 9, tap = rem % 9;
        int dy = tap / 3, dx = tap % 3;
        long long widx;
        float sgn;
        if (conjt) { widx = ((long long)(b * CI + i) * CO + o) * 9 + dx * 3 + dy; sgn = -1.f; }
        else       { widx = ((long long)(b * CO + o) * CI + i) * 9 + dy * 3 + dx; sgn =  1.f; }
        ws[t] = make_float2(wr[widx], sgn * wi[widx]);
    }
    __syncthreads();
    int q = blockIdx.x * 16 + threadIdx.x;
    int p = blockIdx.y * 16 + threadIdx.y;
    if (p >= NG || q >= NG) return;
    const float2* Xb = X + (long long)b * CI * NN;
    float2 acc[CO];
#pragma unroll
    for (int o = 0; o < CO; o++) acc[o] = make_float2(0.f, 0.f);
#pragma unroll
    for (int i = 0; i < CI; i++) {
#pragma unroll
        for (int dy = 0; dy < 3; dy++) {
            int ii = p + dy - 1;
#pragma unroll
            for (int dx = 0; dx < 3; dx++) {
                int jj = q + dx - 1;
                float2 xv = make_float2(0.f, 0.f);
                if (ii >= 0 && ii < NG && jj >= 0 && jj < NG)
                    xv = Xb[(long long)i * NN + (long long)ii * NG + jj];
                int tap = dy * 3 + dx;
#pragma unroll
                for (int o = 0; o < CO; o++)
                    acc[o] = cmad(acc[o], xv, ws[(o * CI + i) * 9 + tap]);
            }
        }
    }
    float2* Yb = Y + (long long)b * CO * NN;
    long long po = (long long)p * NG + q;
#pragma unroll
    for (int o = 0; o < CO; o++) Yb[(long long)o * NN + po] = acc[o];
}

// ---------------------------------------------------------------------------
// out = rh3 * wt * ik2  (elementwise, in place on g_cC)
// ---------------------------------------------------------------------------
__global__ void k_wtik(float2* __restrict__ C, const float* __restrict__ wtr,
                       const float* __restrict__ wti)
{
    int b = blockIdx.z;
    int q = blockIdx.x * 16 + threadIdx.x;
    int p = blockIdx.y * 16 + threadIdx.y;
    if (p >= NG || q >= NG) return;
    long long o = (long long)b * NN + (long long)p * NG + q;
    float2 c = C[o];
    float wr = wtr[o], wi = wti[o];
    float dp = (float)(p - 256), dq = (float)(q - 256);
    float s = dp * dp + dq * dq;
    const float pi2 = 9.869604401089358f;   // pi^2
    float ik = (s == 0.f) ? 1.f : 1.f / (pi2 * s);
    float2 r;
    r.x = (c.x * wr - c.y * wi) * ik;
    r.y = (c.x * wi + c.y * wr) * ik;
    C[o] = r;
}

// ---------------------------------------------------------------------------
// Reductions (deterministic, double accumulation)
// ---------------------------------------------------------------------------
__global__ __launch_bounds__(256)
void k_alpha_part(const float* __restrict__ r, const float* __restrict__ e,
                  const float* __restrict__ a, double* __restrict__ p1,
                  double* __restrict__ p2)
{
    int b = blockIdx.y;
    const float* rb = r + (long long)b * NN;
    const float* eb = e + (long long)b * NN;
    const float* ab = a + (long long)b * NCC;
    double num = 0.0, den = 0.0;
    for (long long idx = (long long)blockIdx.x * 256 + threadIdx.x; idx < NN;
         idx += (long long)gridDim.x * 256) {
        int i = (int)(idx / NG), j = (int)(idx - (long long)i * NG);
        float ev = eb[idx];
        num += (double)(rb[idx] * ev);
        if (i > 0 && j > 0 && i < NG - 1 && j < NG - 1) {
            float d = darcy_at(eb, ab, i, j);
            den += (double)(d * ev);
        }
    }
    __shared__ double s1[256], s2[256];
    int t = threadIdx.x;
    s1[t] = num; s2[t] = den;
    __syncthreads();
    for (int s = 128; s > 0; s >>= 1) {
        if (t < s) { s1[t] += s1[t + s]; s2[t] += s2[t + s]; }
        __syncthreads();
    }
    if (t == 0) { p1[b * NBLK_A + blockIdx.x] = s1[0]; p2[b * NBLK_A + blockIdx.x] = s2[0]; }
}

__global__ void k_alpha_fin(const double* __restrict__ p1,
                            const double* __restrict__ p2,
                            float* __restrict__ alpha)
{
    int b = blockIdx.x;
    __shared__ double s1[256], s2[256];
    double n = 0.0, d = 0.0;
    for (int i = threadIdx.x; i < NBLK_A; i += 256) {
        n += p1[b * NBLK_A + i]; d += p2[b * NBLK_A + i];
    }
    int t = threadIdx.x;
    s1[t] = n; s2[t] = d;
    __syncthreads();
    for (int s = 128; s > 0; s >>= 1) {
        if (t < s) { s1[t] += s1[t + s]; s2[t] += s2[t + s]; }
        __syncthreads();
    }
    if (t == 0) alpha[b] = (float)(s1[0] / s2[0]);
}

__global__ void k_update(float* __restrict__ x, const float* __restrict__ e,
                         const float* __restrict__ alpha)
{
    int b = blockIdx.z;
    int j = blockIdx.x * 16 + threadIdx.x + 1;
    int i = blockIdx.y * 16 + threadIdx.y + 1;
    if (i > NI || j > NI) return;
    long long o = (long long)b * NN + (long long)i * NG + j;
    x[o] = fmaf(alpha[b], e[o], x[o]);
}

__global__ __launch_bounds__(256)
void k_norm_part(const float* __restrict__ r, const float* __restrict__ f,
                 double* __restrict__ p1, double* __restrict__ p2)
{
    double sr = 0.0, sf = 0.0;
    long long tot = (long long)NB * NN;
    for (long long idx = (long long)blockIdx.x * 256 + threadIdx.x; idx < tot;
         idx += (long long)gridDim.x * 256) {
        float rv = r[idx], fv = f[idx];
        sr += (double)rv * rv;
        sf += (double)fv * fv;
    }
    __shared__ double s1[256], s2[256];
    int t = threadIdx.x;
    s1[t] = sr; s2[t] = sf;
    __syncthreads();
    for (int s = 128; s > 0; s >>= 1) {
        if (t < s) { s1[t] += s1[t + s]; s2[t] += s2[t + s]; }
        __syncthreads();
    }
    if (t == 0) { p1[blockIdx.x] = s1[0]; p2[blockIdx.x] = s2[0]; }
}

__global__ void k_norm_fin(const double* __restrict__ p1,
                           const double* __restrict__ p2,
                           float* __restrict__ out)
{
    __shared__ double s1[256], s2[256];
    double a = 0.0, b = 0.0;
    for (int i = threadIdx.x; i < NBLK_N; i += 256) { a += p1[i]; b += p2[i]; }
    int t = threadIdx.x;
    s1[t] = a; s2[t] = b;
    __syncthreads();
    for (int s = 128; s > 0; s >>= 1) {
        if (t < s) { s1[t] += s1[t + s]; s2[t] += s2[t + s]; }
        __syncthreads();
    }
    if (t == 0) out[0] = (float)sqrt(s1[0] / s2[0]);
}

// ---------------------------------------------------------------------------
// Host orchestration
// ---------------------------------------------------------------------------
template<typename T>
static T* sym_addr(const void* sym)
{
    void* p = nullptr;
    cudaGetSymbolAddress(&p, sym);
    return (T*)p;
}

extern "C" void kernel_launch(void* const* d_in, const int* in_sizes, int n_in,
                              void* d_out, int out_size)
{
    const float* f    = (const float*)d_in[0];
    const float* coef = (const float*)d_in[1];
    // d_in[2] = u (unused)
    const float* w1r = (const float*)d_in[3];
    const float* w1i = (const float*)d_in[4];
    const float* w2r = (const float*)d_in[5];
    const float* w2i = (const float*)d_in[6];
    const float* w3r = (const float*)d_in[7];
    const float* w3i = (const float*)d_in[8];
    const float* wtr = (const float*)d_in[9];
    const float* wti = (const float*)d_in[10];
    // d_in[11] = epoch (fixed 101 -> K=2)

    float*  x    = sym_addr<float>(g_x);
    float*  x2   = sym_addr<float>(g_x2);
    float*  r    = sym_addr<float>(g_r);
    float*  e    = sym_addr<float>(g_e);
    float*  dinv = sym_addr<float>(g_dinv);
    float*  S    = sym_addr<float>(g_S);
    float*  St   = sym_addr<float>(g_St);
    float2* G    = sym_addr<float2>(g_G);
    float2* Gt   = sym_addr<float2>(g_Gt);
    float*  U    = sym_addr<float>(g_U);
    float2* cA   = sym_addr<float2>(g_cA);
    float2* cB   = sym_addr<float2>(g_cB);
    float2* cC   = sym_addr<float2>(g_cC);
    float2* W    = sym_addr<float2>(g_W);
    double* pd1  = sym_addr<double>(g_pd1);
    double* pd2  = sym_addr<double>(g_pd2);
    float*  alph = sym_addr<float>(g_alpha);

    dim3 blk2(16, 16);
    dim3 gInt((NI + 15) / 16, (NI + 15) / 16, NB);   // interior nodes
    dim3 gFull((NG + 15) / 16, (NG + 15) / 16, NB);  // all nodes

    // ---- setup ----
    {
        long long tot = (long long)NB * NN;
        k_zero3<<<(int)((tot + 255) / 256), 256>>>(x, x2, e);
        int nSG = NG * NI;
        k_precS<<<(nSG + 255) / 256, 256>>>(S, St);
        k_precG<<<(nSG + 255) / 256, 256>>>(G, Gt);
        k_dinv<<<gInt, blk2>>>(coef, dinv);
    }

    float* xa = x;
    float* xb = x2;

    for (int step = 0; step < KSTEPS; step++) {
        // ---- 10 Jacobi sweeps ----
        for (int it = 0; it < 10; it++) {
            k_jacobi<<<gInt, blk2>>>(xa, xb, f, coef, dinv);
            float* tmp = xa; xa = xb; xb = tmp;
        }
        // ---- residual ----
        k_resid<<<gFull, blk2>>>(xa, f, coef, r);

        // ---- H_apply: forward sine transform (rh = -(1/512^2) S * r_int * S^T) ----
        // U = r_int(511x511) * Sjp(511x513)
        {
            dim3 g((NG + 63) / 64, (NI + 63) / 64, NB);
            k_sgemm<false><<<g, 256>>>(r + NG + 1, NG, NN,
                                       St, NG, 0,
                                       U, NG, NIG,
                                       NI, NG, NI, 1.f);
        }
        // rh = Ssp(513x511) * U(511x513), scaled, write complex(im=0) into cC
        {
            dim3 g((NG + 63) / 64, (NG + 63) / 64, NB);
            k_sgemm<true><<<g, 256>>>(S, NI, 0,
                                      U, NG, NIG,
                                      cC, NG, NN,
                                      NG, NG, NI, -1.f / (512.f * 512.f));
        }

        // ---- 3 complex convs forward ----
        k_conv<4, 1><<<gFull, blk2>>>(cC, cA, w1r, w1i, 0);
        k_conv<4, 4><<<gFull, blk2>>>(cA, cB, w2r, w2i, 0);
        k_conv<1, 4><<<gFull, blk2>>>(cB, cC, w3r, w3i, 0);

        // ---- spectral multiply ----
        k_wtik<<<gFull, blk2>>>(cC, wtr, wti);

        // ---- 3 complex convs backward (conjT) ----
        k_conv<4, 1><<<gFull, blk2>>>(cC, cA, w3r, w3i, 1);
        k_conv<4, 4><<<gFull, blk2>>>(cA, cB, w2r, w2i, 1);
        k_conv<1, 4><<<gFull, blk2>>>(cB, cC, w1r, w1i, 1);

        // ---- inverse transform: E = Re(G * out * G^T) -> e interior ----
        // W = out(513x513) * Gt(513x511)
        {
            dim3 g((NI + 63) / 64, (NG + 63) / 64, NB);
            k_cgemm<false><<<g, 256>>>(cC, NG, NN,
                                       Gt, NI, 0,
                                       W, NI, NIG,
                                       NG, NI, NG);
        }
        // e_int = Re(G(511x513) * W(513x511))
        {
            dim3 g((NI + 63) / 64, (NI + 63) / 64, NB);
            k_cgemm<true><<<g, 256>>>(G, NG, 0,
                                      W, NI, NIG,
                                      e + NG + 1, NG, NN,
                                      NI, NI, NG);
        }

        // ---- alpha = sum(r*e) / sum(darcy(e)*e), then x += alpha*e ----
        {
            dim3 g(NBLK_A, NB);
            k_alpha_part<<<g, 256>>>(r, e, coef, pd1, pd2);
            k_alpha_fin<<<NB, 256>>>(pd1, pd2, alph);
            k_update<<<gInt, blk2>>>(xa, e, alph);
        }
    }

    // ---- final relative residual norm ----
    k_resid<<<gFull, blk2>>>(xa, f, coef, r);
    k_norm_part<<<NBLK_N, 256>>>(r, f, pd1, pd2);
    k_norm_fin<<<1, 256>>>(pd1, pd2, (float*)d_out);
}